// round 13
// baseline (speedup 1.0000x reference)
#include <cuda_runtime.h>
#include <cuda_bf16.h>
#include <cuda_pipeline_primitives.h>
#include <cstdint>

#define HID  200
#define DD   8
#define SB   8            // samples per block
#define CG   25           // column groups (25 * 8 = 200 cols)
#define NC   8            // columns per thread
#define NTH  224          // 8 samples * 25 groups = 7 warps
#define NW   7
#define SLOT 12           // floats per (col,sample) record (0-7 dirs, 8-9 primal dup)
#define PADK 100          // floats per col row: SB*SLOT=96 +4 pad
#define CH   8            // k-rows per W stage chunk
#define NCH  (HID / CH)   // 25 chunks
#define EPSV 0.1f
#define DSMEM (HID * PADK * 4)   // 80000 bytes dynamic

// Pre-transposed weights (device scratch; no allocation), 16B-aligned for cp.async
__device__ __align__(16) float g_W1T[HID * HID];
__device__ __align__(16) float g_W2T[HID * HID];

__global__ void transposeW(const float* __restrict__ W1, const float* __restrict__ W2) {
    int idx = blockIdx.x * blockDim.x + threadIdx.x;
    if (idx < HID * HID) {
        int r = idx / HID, c = idx % HID;
        g_W1T[c * HID + r] = W1[idx];
        g_W2T[c * HID + r] = W2[idx];
    }
}

typedef unsigned long long u64;
typedef unsigned int u32;

__device__ __forceinline__ u64 pack2(float lo, float hi) {
    u64 r; asm("mov.b64 %0, {%1, %2};" : "=l"(r) : "f"(lo), "f"(hi)); return r;
}
__device__ __forceinline__ float2 unpack2(u64 v) {
    float2 r; asm("mov.b64 {%0, %1}, %2;" : "=f"(r.x), "=f"(r.y) : "l"(v)); return r;
}
__device__ __forceinline__ u64 fma2(u64 a, u64 b, u64 c) {
    u64 d; asm("fma.rn.f32x2 %0, %1, %2, %3;" : "=l"(d) : "l"(a), "l"(b), "l"(c)); return d;
}

__device__ __forceinline__ float sigm(float x)     { return 1.0f / (1.0f + expf(-x)); }
__device__ __forceinline__ float softplusf(float x){ return fmaxf(x, 0.0f) + log1pf(expf(-fabsf(x))); }

__device__ __forceinline__ u32 bfpack(float a, float b) {
    __nv_bfloat162 p = __floats2bfloat162_rn(a, b);
    return *reinterpret_cast<u32*>(&p);
}
__device__ __forceinline__ float2 bfunpack(u32 v) {
    return __bfloat1622float2(*reinterpret_cast<__nv_bfloat162*>(&v));
}

// One k-step: A from db (per-sample), W row from staged smem. 36 FFMA2.
#define GEMM_STEP_S(kk, wq)                                                     \
    {                                                                           \
        const float* ap = &db[(kk) * PADK + s * SLOT];                          \
        float4 a0 = *reinterpret_cast<const float4*>(ap);                       \
        float4 a1 = *reinterpret_cast<const float4*>(ap + 4);                   \
        u64 ab8 = *reinterpret_cast<const u64*>(ap + 8);                        \
        float4 w0 = *reinterpret_cast<const float4*>(wq);                       \
        float4 w1 = *reinterpret_cast<const float4*>((wq) + 4);                 \
        u64 uw0 = pack2(w0.x, w0.y), uw1 = pack2(w0.z, w0.w);                   \
        u64 uw2 = pack2(w1.x, w1.y), uw3 = pack2(w1.z, w1.w);                   \
        float av[8] = {a0.x, a0.y, a0.z, a0.w, a1.x, a1.y, a1.z, a1.w};         \
        _Pragma("unroll")                                                       \
        for (int r = 0; r < 8; r++) {                                           \
            u64 ab = pack2(av[r], av[r]);                                       \
            Cp[r][0] = fma2(ab, uw0, Cp[r][0]);                                 \
            Cp[r][1] = fma2(ab, uw1, Cp[r][1]);                                 \
            Cp[r][2] = fma2(ab, uw2, Cp[r][2]);                                 \
            Cp[r][3] = fma2(ab, uw3, Cp[r][3]);                                 \
        }                                                                       \
        Cp[8][0] = fma2(ab8, uw0, Cp[8][0]);                                    \
        Cp[8][1] = fma2(ab8, uw1, Cp[8][1]);                                    \
        Cp[8][2] = fma2(ab8, uw2, Cp[8][2]);                                    \
        Cp[8][3] = fma2(ab8, uw3, Cp[8][3]);                                    \
    }

// Stage one CH-row chunk of W into wst[buf] (all threads participate).
#define STAGE_W(Wb, ch, buf)                                                    \
    {                                                                           \
        const float* _src = (Wb) + (ch) * (CH * HID);                           \
        float* _dst = &wst[buf][0];                                             \
        for (int i = tid; i < (CH * HID) / 4; i += NTH)                         \
            __pipeline_memcpy_async(_dst + i * 4, _src + i * 4, 16);            \
        __pipeline_commit();                                                    \
    }

// Full phase: cp.async double-buffered W staging; compute guarded by act.
// Must be executed by ALL threads (contains __syncthreads).
#define GEMM_PHASE(Wb)                                                          \
    {                                                                           \
        _Pragma("unroll")                                                       \
        for (int r = 0; r < 9; r++) {                                           \
            _Pragma("unroll")                                                   \
            for (int j = 0; j < 4; j++) Cp[r][j] = 0ull;                        \
        }                                                                       \
        STAGE_W(Wb, 0, 0);                                                      \
        for (int ch = 0; ch < NCH; ch++) {                                      \
            if (ch + 1 < NCH) {                                                 \
                STAGE_W(Wb, ch + 1, (ch + 1) & 1);                              \
                __pipeline_wait_prior(1);                                       \
            } else {                                                            \
                __pipeline_wait_prior(0);                                       \
            }                                                                   \
            __syncthreads();                                                    \
            if (act) {                                                          \
                const float* wbse = &wst[ch & 1][col0];                         \
                _Pragma("unroll")                                               \
                for (int kk = 0; kk < CH; kk++)                                 \
                    GEMM_STEP_S(ch * CH + kk, wbse + kk * HID);                 \
            }                                                                   \
            __syncthreads();                                                    \
        }                                                                       \
    }

__global__ void __launch_bounds__(NTH, 2) lnn_kernel(
    const float* __restrict__ z,
    const float* __restrict__ W0, const float* __restrict__ b0,
    const float* __restrict__ W1, const float* __restrict__ b1,
    const float* __restrict__ W2, const float* __restrict__ b2,
    const float* __restrict__ W3,
    float* __restrict__ out, int n)
{
    extern __shared__ float db[];              // [HID][PADK]
    __shared__ __align__(16) float wst[2][CH * HID];   // staged W chunks (12.8 KB)
    __shared__ uint4 th2b[HID][SB];            // bf16-packed th2 (8 dirs per (col,s))
    __shared__ float shz[SB][16];
    __shared__ float sh_g[SB][16];
    __shared__ float sh_H[SB][8][16];

    const int tid  = threadIdx.x;
    const int s    = tid & 7;              // sample within block
    const int g    = tid >> 3;             // column group
    const int col0 = g * NC;
    const bool act = (g < CG);
    const int base = blockIdx.x * SB;
    const int warp = tid >> 5, lane = tid & 31;

    for (int i = tid; i < SB * 16; i += NTH) {
        int smp = base + (i >> 4);
        if (smp >= n) smp = n - 1;
        shz[i >> 4][i & 15] = z[smp * 16 + (i & 15)];
    }
    __syncthreads();

    float s1r[NC], s2r[NC];
    u64 Cp[9][4];

    // ---------- phase 0: x1 = z@W0 + b0 ; seed tangents ----------
    if (act) {
        float xa[NC];
        *reinterpret_cast<float4*>(&xa[0]) = *reinterpret_cast<const float4*>(&b0[col0]);
        *reinterpret_cast<float4*>(&xa[4]) = *reinterpret_cast<const float4*>(&b0[col0 + 4]);
        #pragma unroll
        for (int m = 0; m < 16; m++) {
            float zm = shz[s][m];
            float wv[NC];
            *reinterpret_cast<float4*>(&wv[0]) = *reinterpret_cast<const float4*>(&W0[m * HID + col0]);
            *reinterpret_cast<float4*>(&wv[4]) = *reinterpret_cast<const float4*>(&W0[m * HID + col0 + 4]);
            #pragma unroll
            for (int c = 0; c < NC; c++) xa[c] = fmaf(zm, wv[c], xa[c]);
        }
        #pragma unroll
        for (int c = 0; c < NC; c++) {
            s1r[c] = sigm(xa[c]);
            float h = softplusf(xa[c]);
            db[(col0 + c) * PADK + s * SLOT + 8] = h;
            db[(col0 + c) * PADK + s * SLOT + 9] = h;
        }
        #pragma unroll
        for (int d = 0; d < DD; d++) {
            float wv[NC];
            *reinterpret_cast<float4*>(&wv[0]) = *reinterpret_cast<const float4*>(&W0[(DD + d) * HID + col0]);
            *reinterpret_cast<float4*>(&wv[4]) = *reinterpret_cast<const float4*>(&W0[(DD + d) * HID + col0 + 4]);
            #pragma unroll
            for (int c = 0; c < NC; c++)
                db[(col0 + c) * PADK + s * SLOT + d] = s1r[c] * wv[c];  // th1
        }
    }
    __syncthreads();

    // ---------- phase 1: stream W1 -> x2 + t2 ----------
    GEMM_PHASE(W1);
    if (act) {
        float bw[NC];
        *reinterpret_cast<float4*>(&bw[0]) = *reinterpret_cast<const float4*>(&b1[col0]);
        *reinterpret_cast<float4*>(&bw[4]) = *reinterpret_cast<const float4*>(&b1[col0 + 4]);
        #pragma unroll
        for (int j = 0; j < 4; j++) {
            float2 xp = unpack2(Cp[8][j]);
            float xlo = xp.x + bw[2 * j], xhi = xp.y + bw[2 * j + 1];
            float slo = sigm(xlo), shi = sigm(xhi);
            s2r[2 * j] = slo; s2r[2 * j + 1] = shi;
            float vlo[9], vhi[9];
            #pragma unroll
            for (int d = 0; d < DD; d++) {
                float2 t = unpack2(Cp[d][j]);
                vlo[d] = slo * t.x; vhi[d] = shi * t.y;     // th2 = s2*t2
            }
            vlo[8] = softplusf(xlo); vhi[8] = softplusf(xhi);  // h2
            float* plo = &db[(col0 + 2 * j) * PADK + s * SLOT];
            float* phi = &db[(col0 + 2 * j + 1) * PADK + s * SLOT];
            *reinterpret_cast<float4*>(plo)     = make_float4(vlo[0], vlo[1], vlo[2], vlo[3]);
            *reinterpret_cast<float4*>(plo + 4) = make_float4(vlo[4], vlo[5], vlo[6], vlo[7]);
            plo[8] = vlo[8]; plo[9] = vlo[8];
            *reinterpret_cast<float4*>(phi)     = make_float4(vhi[0], vhi[1], vhi[2], vhi[3]);
            *reinterpret_cast<float4*>(phi + 4) = make_float4(vhi[4], vhi[5], vhi[6], vhi[7]);
            phi[8] = vhi[8]; phi[9] = vhi[8];
            // persist th2 in bf16 for phase-3 correction term
            uint4 tl, th;
            tl.x = bfpack(vlo[0], vlo[1]); tl.y = bfpack(vlo[2], vlo[3]);
            tl.z = bfpack(vlo[4], vlo[5]); tl.w = bfpack(vlo[6], vlo[7]);
            th.x = bfpack(vhi[0], vhi[1]); th.y = bfpack(vhi[2], vhi[3]);
            th.z = bfpack(vhi[4], vhi[5]); th.w = bfpack(vhi[6], vhi[7]);
            th2b[col0 + 2 * j][s] = tl;
            th2b[col0 + 2 * j + 1][s] = th;
        }
    }
    __syncthreads();

    // ---------- phase 2: stream W2 -> x3 + t3 ----------
    GEMM_PHASE(W2);
    if (act) {
        float bw[NC], w3v[NC];
        *reinterpret_cast<float4*>(&bw[0])  = *reinterpret_cast<const float4*>(&b2[col0]);
        *reinterpret_cast<float4*>(&bw[4])  = *reinterpret_cast<const float4*>(&b2[col0 + 4]);
        *reinterpret_cast<float4*>(&w3v[0]) = *reinterpret_cast<const float4*>(&W3[col0]);
        *reinterpret_cast<float4*>(&w3v[4]) = *reinterpret_cast<const float4*>(&W3[col0 + 4]);
        #pragma unroll
        for (int j = 0; j < 4; j++) {
            float2 xp = unpack2(Cp[8][j]);
            float xlo = xp.x + bw[2 * j], xhi = xp.y + bw[2 * j + 1];
            float slo = sigm(xlo), shi = sigm(xhi);
            float clo = w3v[2 * j] * slo * (1.0f - slo);
            float chi = w3v[2 * j + 1] * shi * (1.0f - shi);
            float vlo[9], vhi[9];
            #pragma unroll
            for (int d = 0; d < DD; d++) {
                float2 t = unpack2(Cp[d][j]);
                vlo[d] = clo * t.x; vhi[d] = chi * t.y;     // delta-d3
            }
            vlo[8] = w3v[2 * j] * slo; vhi[8] = w3v[2 * j + 1] * shi;   // d3
            float* plo = &db[(col0 + 2 * j) * PADK + s * SLOT];
            float* phi = &db[(col0 + 2 * j + 1) * PADK + s * SLOT];
            *reinterpret_cast<float4*>(plo)     = make_float4(vlo[0], vlo[1], vlo[2], vlo[3]);
            *reinterpret_cast<float4*>(plo + 4) = make_float4(vlo[4], vlo[5], vlo[6], vlo[7]);
            plo[8] = vlo[8]; plo[9] = vlo[8];
            *reinterpret_cast<float4*>(phi)     = make_float4(vhi[0], vhi[1], vhi[2], vhi[3]);
            *reinterpret_cast<float4*>(phi + 4) = make_float4(vhi[4], vhi[5], vhi[6], vhi[7]);
            phi[8] = vhi[8]; phi[9] = vhi[8];
        }
    }
    __syncthreads();

    // ---------- phase 3: stream W2^T -> u2 + r2 ----------
    GEMM_PHASE(g_W2T);
    if (act) {
        // delta-d2 = s2*r2 + (1-s2)*u2*th2   (th2 from bf16 side-buffer)
        #pragma unroll
        for (int j = 0; j < 4; j++) {
            float2 up = unpack2(Cp[8][j]);     // u2 pair
            float slo = s2r[2 * j], shi = s2r[2 * j + 1];
            float klo = (1.0f - slo) * up.x, khi = (1.0f - shi) * up.y;
            uint4 tlv = th2b[col0 + 2 * j][s];
            uint4 thv = th2b[col0 + 2 * j + 1][s];
            float tlo[8], thi[8];
            { float2 p; p = bfunpack(tlv.x); tlo[0] = p.x; tlo[1] = p.y;
              p = bfunpack(tlv.y); tlo[2] = p.x; tlo[3] = p.y;
              p = bfunpack(tlv.z); tlo[4] = p.x; tlo[5] = p.y;
              p = bfunpack(tlv.w); tlo[6] = p.x; tlo[7] = p.y;
              p = bfunpack(thv.x); thi[0] = p.x; thi[1] = p.y;
              p = bfunpack(thv.y); thi[2] = p.x; thi[3] = p.y;
              p = bfunpack(thv.z); thi[4] = p.x; thi[5] = p.y;
              p = bfunpack(thv.w); thi[6] = p.x; thi[7] = p.y; }
            float vlo[9], vhi[9];
            #pragma unroll
            for (int d = 0; d < DD; d++) {
                float2 r = unpack2(Cp[d][j]);
                vlo[d] = fmaf(slo, r.x, klo * tlo[d]);
                vhi[d] = fmaf(shi, r.y, khi * thi[d]);
            }
            vlo[8] = slo * up.x; vhi[8] = shi * up.y;   // d2
            float* plo = &db[(col0 + 2 * j) * PADK + s * SLOT];
            float* phi = &db[(col0 + 2 * j + 1) * PADK + s * SLOT];
            *reinterpret_cast<float4*>(plo)     = make_float4(vlo[0], vlo[1], vlo[2], vlo[3]);
            *reinterpret_cast<float4*>(plo + 4) = make_float4(vlo[4], vlo[5], vlo[6], vlo[7]);
            plo[8] = vlo[8]; plo[9] = vlo[8];
            *reinterpret_cast<float4*>(phi)     = make_float4(vhi[0], vhi[1], vhi[2], vhi[3]);
            *reinterpret_cast<float4*>(phi + 4) = make_float4(vhi[4], vhi[5], vhi[6], vhi[7]);
            phi[8] = vhi[8]; phi[9] = vhi[8];
        }
    }
    __syncthreads();

    // ---------- phase 4: stream W1^T -> u1 + r1 ----------
    GEMM_PHASE(g_W1T);
    if (act) {
        float u1[NC], co[NC];
        #pragma unroll
        for (int j = 0; j < 4; j++) {
            float2 up = unpack2(Cp[8][j]);
            u1[2 * j] = up.x; u1[2 * j + 1] = up.y;
        }
        #pragma unroll
        for (int c = 0; c < NC; c++) {
            co[c] = s1r[c] * (1.0f - s1r[c]) * u1[c];
            db[(col0 + c) * PADK + s * SLOT + 8] = s1r[c] * u1[c];   // d1
        }
        #pragma unroll
        for (int d = 0; d < DD; d++) {
            float wv[NC];
            *reinterpret_cast<float4*>(&wv[0]) = *reinterpret_cast<const float4*>(&W0[(DD + d) * HID + col0]);
            *reinterpret_cast<float4*>(&wv[4]) = *reinterpret_cast<const float4*>(&W0[(DD + d) * HID + col0 + 4]);
            #pragma unroll
            for (int j = 0; j < 4; j++) {
                float2 r = unpack2(Cp[d][j]);
                db[(col0 + 2 * j) * PADK + s * SLOT + d]     = fmaf(s1r[2 * j],     r.x, co[2 * j]     * wv[2 * j]);
                db[(col0 + 2 * j + 1) * PADK + s * SLOT + d] = fmaf(s1r[2 * j + 1], r.y, co[2 * j + 1] * wv[2 * j + 1]);
            }
        }
    }
    __syncthreads();

    // ---------- final dots ----------
    for (int idx = warp; idx < SB * 16; idx += NW) {
        int ss = idx >> 4, m = idx & 15;
        float a = 0.0f;
        for (int k = lane; k < HID; k += 32)
            a = fmaf(W0[m * HID + k], db[k * PADK + ss * SLOT + 8], a);
        #pragma unroll
        for (int off = 16; off > 0; off >>= 1) a += __shfl_xor_sync(0xffffffffu, a, off);
        if (lane == 0) sh_g[ss][m] = a;
    }
    for (int idx = warp; idx < SB * 128; idx += NW) {
        int ss = idx >> 7;
        int r = idx & 127;
        int d = r >> 4, m = r & 15;
        float a = 0.0f;
        for (int k = lane; k < HID; k += 32)
            a = fmaf(W0[m * HID + k], db[k * PADK + ss * SLOT + d], a);
        #pragma unroll
        for (int off = 16; off > 0; off >>= 1) a += __shfl_xor_sync(0xffffffffu, a, off);
        if (lane == 0) sh_H[ss][d][m] = a;
    }
    __syncthreads();

    // ---------- per-sample 8x8 solve + output ----------
    if (tid < SB && base + tid < n) {
        const int ss = tid;
        float Mt[DD][DD], Fv[DD], av[DD], vv[DD];
        #pragma unroll
        for (int c = 0; c < DD; c++) vv[c] = shz[ss][DD + c];
        for (int r = 0; r < DD; r++)
            for (int c = 0; c < DD; c++)
                Mt[r][c] = sh_H[ss][r][DD + c] + ((r == c) ? 2.0f * EPSV : 0.0f);
        for (int p = 0; p < DD; p++) {
            float f = sh_g[ss][p];
            for (int c = 0; c < DD; c++) f -= sh_H[ss][p][c] * vv[c];
            Fv[p] = f;
        }
        for (int col = 0; col < DD; col++) {
            int piv = col; float best = fabsf(Mt[col][col]);
            for (int r = col + 1; r < DD; r++) {
                float m = fabsf(Mt[r][col]);
                if (m > best) { best = m; piv = r; }
            }
            if (piv != col) {
                for (int c = col; c < DD; c++) { float t = Mt[col][c]; Mt[col][c] = Mt[piv][c]; Mt[piv][c] = t; }
                float t = Fv[col]; Fv[col] = Fv[piv]; Fv[piv] = t;
            }
            float inv = 1.0f / Mt[col][col];
            for (int r = col + 1; r < DD; r++) {
                float fac = Mt[r][col] * inv;
                for (int c = col; c < DD; c++) Mt[r][c] -= fac * Mt[col][c];
                Fv[r] -= fac * Fv[col];
            }
        }
        for (int r = DD - 1; r >= 0; r--) {
            float x = Fv[r];
            for (int c = r + 1; c < DD; c++) x -= Mt[r][c] * av[c];
            av[r] = x / Mt[r][r];
        }
        const int gi = (base + ss) * 16;
        #pragma unroll
        for (int j = 0; j < DD; j++) out[gi + j] = vv[j];
        #pragma unroll
        for (int j = 0; j < DD; j++) out[gi + DD + j] = av[j];
    }
}

extern "C" void kernel_launch(void* const* d_in, const int* in_sizes, int n_in,
                              void* d_out, int out_size) {
    const float* z  = (const float*)d_in[1];
    const float* W0 = (const float*)d_in[2];
    const float* b0 = (const float*)d_in[3];
    const float* W1 = (const float*)d_in[4];
    const float* b1 = (const float*)d_in[5];
    const float* W2 = (const float*)d_in[6];
    const float* b2 = (const float*)d_in[7];
    const float* W3 = (const float*)d_in[8];
    float* out = (float*)d_out;

    const int n = in_sizes[1] / 16;

    cudaFuncSetAttribute(lnn_kernel, cudaFuncAttributeMaxDynamicSharedMemorySize, DSMEM);

    transposeW<<<(HID * HID + 255) / 256, 256>>>(W1, W2);

    const int blocks = (n + SB - 1) / SB;
    lnn_kernel<<<blocks, NTH, DSMEM>>>(z, W0, b0, W1, b1, W2, b2, W3, out, n);
}

// round 14
// speedup vs baseline: 1.4298x; 1.4298x over previous
#include <cuda_runtime.h>
#include <cuda_bf16.h>
#include <cstdint>

#define HID  200
#define DD   8
#define SB   8            // samples per block
#define NG   50           // column groups (50 * 4 = 200 cols)
#define NC   4            // columns per thread
#define NTH  416          // 13 warps; 400 active in GEMM (50 groups x 8 samples)
#define NW   13
#define SLOT 12           // floats per (col,sample) record (0-7 dirs, 8-9 primal dup)
#define PADK 100          // floats per col row: SB*SLOT=96 +4 pad
#define EPSV 0.1f
#define DSMEM (HID * PADK * 4)   // 80000 bytes dynamic

// Pre-transposed weights (device scratch; no allocation)
__device__ float g_W1T[HID * HID];
__device__ float g_W2T[HID * HID];

__global__ void transposeW(const float* __restrict__ W1, const float* __restrict__ W2) {
    int idx = blockIdx.x * blockDim.x + threadIdx.x;
    if (idx < HID * HID) {
        int r = idx / HID, c = idx % HID;
        g_W1T[c * HID + r] = W1[idx];
        g_W2T[c * HID + r] = W2[idx];
    }
}

typedef unsigned long long u64;
typedef unsigned int u32;

__device__ __forceinline__ u64 pack2(float lo, float hi) {
    u64 r; asm("mov.b64 %0, {%1, %2};" : "=l"(r) : "f"(lo), "f"(hi)); return r;
}
__device__ __forceinline__ float2 unpack2(u64 v) {
    float2 r; asm("mov.b64 {%0, %1}, %2;" : "=f"(r.x), "=f"(r.y) : "l"(v)); return r;
}
__device__ __forceinline__ u64 fma2(u64 a, u64 b, u64 c) {
    u64 d; asm("fma.rn.f32x2 %0, %1, %2, %3;" : "=l"(d) : "l"(a), "l"(b), "l"(c)); return d;
}

__device__ __forceinline__ float sigm(float x)     { return 1.0f / (1.0f + expf(-x)); }
__device__ __forceinline__ float softplusf(float x){ return fmaxf(x, 0.0f) + log1pf(expf(-fabsf(x))); }

__device__ __forceinline__ u32 bfpack(float a, float b) {
    __nv_bfloat162 p = __floats2bfloat162_rn(a, b);
    return *reinterpret_cast<u32*>(&p);
}
__device__ __forceinline__ float2 bfunpack(u32 v) {
    return __bfloat1622float2(*reinterpret_cast<__nv_bfloat162*>(&v));
}

// One k-step of the 9-row x 4-col register-tile GEMM using W buffer slot B.
// 18 FFMA2 + 5 LDS + 9 packs.
#define GEMM_STEP_B(kk, B)                                                      \
    {                                                                           \
        const float* ap = &db[(kk) * PADK + s * SLOT];                          \
        float4 a0 = *reinterpret_cast<const float4*>(ap);                       \
        float4 a1 = *reinterpret_cast<const float4*>(ap + 4);                   \
        u64 ab8 = *reinterpret_cast<const u64*>(ap + 8);                        \
        u64 uw0 = pack2(wb[B].x, wb[B].y), uw1 = pack2(wb[B].z, wb[B].w);       \
        float av[8] = {a0.x, a0.y, a0.z, a0.w, a1.x, a1.y, a1.z, a1.w};         \
        _Pragma("unroll")                                                       \
        for (int r = 0; r < 8; r++) {                                           \
            u64 ab = pack2(av[r], av[r]);                                       \
            Cp[r][0] = fma2(ab, uw0, Cp[r][0]);                                 \
            Cp[r][1] = fma2(ab, uw1, Cp[r][1]);                                 \
        }                                                                       \
        Cp[8][0] = fma2(ab8, uw0, Cp[8][0]);                                    \
        Cp[8][1] = fma2(ab8, uw1, Cp[8][1]);                                    \
    }

// Full phase: W double-buffered in registers, 2x-unrolled body, no copies.
#define GEMM_PHASE(Wb)                                                          \
    {                                                                           \
        _Pragma("unroll")                                                       \
        for (int r = 0; r < 9; r++) { Cp[r][0] = 0ull; Cp[r][1] = 0ull; }       \
        const float* wp = &(Wb)[col0];                                          \
        float4 wb[2];                                                           \
        wb[0] = *reinterpret_cast<const float4*>(wp);                           \
        for (int k = 0; k < HID - 2; k += 2) {                                  \
            wb[1] = *reinterpret_cast<const float4*>(wp + HID);                 \
            GEMM_STEP_B(k, 0);                                                  \
            wp += 2 * HID;                                                      \
            wb[0] = *reinterpret_cast<const float4*>(wp);                       \
            GEMM_STEP_B(k + 1, 1);                                              \
        }                                                                       \
        wb[1] = *reinterpret_cast<const float4*>(wp + HID);                     \
        GEMM_STEP_B(HID - 2, 0);                                                \
        GEMM_STEP_B(HID - 1, 1);                                                \
    }

__global__ void __launch_bounds__(NTH, 2) lnn_kernel(
    const float* __restrict__ z,
    const float* __restrict__ W0, const float* __restrict__ b0,
    const float* __restrict__ W1, const float* __restrict__ b1,
    const float* __restrict__ W2, const float* __restrict__ b2,
    const float* __restrict__ W3,
    float* __restrict__ out, int n)
{
    extern __shared__ float db[];              // [HID][PADK]
    __shared__ uint4 th2b[HID][SB];            // bf16-packed th2 (8 dirs per (col,s))
    __shared__ float shz[SB][16];
    __shared__ float sh_g[SB][16];
    __shared__ float sh_H[SB][8][16];

    const int tid  = threadIdx.x;
    const int s    = tid & 7;              // sample within block
    const int g    = tid >> 3;             // column group
    const int col0 = g * NC;
    const bool act = (g < NG);
    const int base = blockIdx.x * SB;
    const int warp = tid >> 5, lane = tid & 31;

    for (int i = tid; i < SB * 16; i += NTH) {
        int smp = base + (i >> 4);
        if (smp >= n) smp = n - 1;
        shz[i >> 4][i & 15] = z[smp * 16 + (i & 15)];
    }
    __syncthreads();

    float s1r[NC], s2r[NC];
    u64 Cp[9][2];

    // ---------- phase 0: x1 = z@W0 + b0 ; seed tangents ----------
    if (act) {
        float xa[NC];
        *reinterpret_cast<float4*>(xa) = *reinterpret_cast<const float4*>(&b0[col0]);
        #pragma unroll
        for (int m = 0; m < 16; m++) {
            float zm = shz[s][m];
            float wv[NC];
            *reinterpret_cast<float4*>(wv) = *reinterpret_cast<const float4*>(&W0[m * HID + col0]);
            #pragma unroll
            for (int c = 0; c < NC; c++) xa[c] = fmaf(zm, wv[c], xa[c]);
        }
        #pragma unroll
        for (int c = 0; c < NC; c++) {
            s1r[c] = sigm(xa[c]);
            float h = softplusf(xa[c]);
            db[(col0 + c) * PADK + s * SLOT + 8] = h;
            db[(col0 + c) * PADK + s * SLOT + 9] = h;
        }
        #pragma unroll
        for (int d = 0; d < DD; d++) {
            float wv[NC];
            *reinterpret_cast<float4*>(wv) = *reinterpret_cast<const float4*>(&W0[(DD + d) * HID + col0]);
            #pragma unroll
            for (int c = 0; c < NC; c++)
                db[(col0 + c) * PADK + s * SLOT + d] = s1r[c] * wv[c];  // th1
        }
    }
    __syncthreads();

    // ---------- phase 1: stream W1 -> x2 + t2 ----------
    if (act) { GEMM_PHASE(W1); }
    __syncthreads();
    if (act) {
        float bw[NC];
        *reinterpret_cast<float4*>(bw) = *reinterpret_cast<const float4*>(&b1[col0]);
        #pragma unroll
        for (int j = 0; j < 2; j++) {
            float2 xp = unpack2(Cp[8][j]);
            float xlo = xp.x + bw[2 * j], xhi = xp.y + bw[2 * j + 1];
            float slo = sigm(xlo), shi = sigm(xhi);
            s2r[2 * j] = slo; s2r[2 * j + 1] = shi;
            float vlo[9], vhi[9];
            #pragma unroll
            for (int d = 0; d < DD; d++) {
                float2 t = unpack2(Cp[d][j]);
                vlo[d] = slo * t.x; vhi[d] = shi * t.y;     // th2 = s2*t2
            }
            vlo[8] = softplusf(xlo); vhi[8] = softplusf(xhi);  // h2
            float* plo = &db[(col0 + 2 * j) * PADK + s * SLOT];
            float* phi = &db[(col0 + 2 * j + 1) * PADK + s * SLOT];
            *reinterpret_cast<float4*>(plo)     = make_float4(vlo[0], vlo[1], vlo[2], vlo[3]);
            *reinterpret_cast<float4*>(plo + 4) = make_float4(vlo[4], vlo[5], vlo[6], vlo[7]);
            plo[8] = vlo[8]; plo[9] = vlo[8];
            *reinterpret_cast<float4*>(phi)     = make_float4(vhi[0], vhi[1], vhi[2], vhi[3]);
            *reinterpret_cast<float4*>(phi + 4) = make_float4(vhi[4], vhi[5], vhi[6], vhi[7]);
            phi[8] = vhi[8]; phi[9] = vhi[8];
            // persist th2 in bf16 for phase-3 correction term
            uint4 tl, th;
            tl.x = bfpack(vlo[0], vlo[1]); tl.y = bfpack(vlo[2], vlo[3]);
            tl.z = bfpack(vlo[4], vlo[5]); tl.w = bfpack(vlo[6], vlo[7]);
            th.x = bfpack(vhi[0], vhi[1]); th.y = bfpack(vhi[2], vhi[3]);
            th.z = bfpack(vhi[4], vhi[5]); th.w = bfpack(vhi[6], vhi[7]);
            th2b[col0 + 2 * j][s] = tl;
            th2b[col0 + 2 * j + 1][s] = th;
        }
    }
    __syncthreads();

    // ---------- phase 2: stream W2 -> x3 + t3 ----------
    if (act) { GEMM_PHASE(W2); }
    __syncthreads();
    if (act) {
        float bw[NC], w3v[NC];
        *reinterpret_cast<float4*>(bw)  = *reinterpret_cast<const float4*>(&b2[col0]);
        *reinterpret_cast<float4*>(w3v) = *reinterpret_cast<const float4*>(&W3[col0]);
        #pragma unroll
        for (int j = 0; j < 2; j++) {
            float2 xp = unpack2(Cp[8][j]);
            float xlo = xp.x + bw[2 * j], xhi = xp.y + bw[2 * j + 1];
            float slo = sigm(xlo), shi = sigm(xhi);
            float clo = w3v[2 * j] * slo * (1.0f - slo);
            float chi = w3v[2 * j + 1] * shi * (1.0f - shi);
            float vlo[9], vhi[9];
            #pragma unroll
            for (int d = 0; d < DD; d++) {
                float2 t = unpack2(Cp[d][j]);
                vlo[d] = clo * t.x; vhi[d] = chi * t.y;     // delta-d3
            }
            vlo[8] = w3v[2 * j] * slo; vhi[8] = w3v[2 * j + 1] * shi;   // d3
            float* plo = &db[(col0 + 2 * j) * PADK + s * SLOT];
            float* phi = &db[(col0 + 2 * j + 1) * PADK + s * SLOT];
            *reinterpret_cast<float4*>(plo)     = make_float4(vlo[0], vlo[1], vlo[2], vlo[3]);
            *reinterpret_cast<float4*>(plo + 4) = make_float4(vlo[4], vlo[5], vlo[6], vlo[7]);
            plo[8] = vlo[8]; plo[9] = vlo[8];
            *reinterpret_cast<float4*>(phi)     = make_float4(vhi[0], vhi[1], vhi[2], vhi[3]);
            *reinterpret_cast<float4*>(phi + 4) = make_float4(vhi[4], vhi[5], vhi[6], vhi[7]);
            phi[8] = vhi[8]; phi[9] = vhi[8];
        }
    }
    __syncthreads();

    // ---------- phase 3: stream W2^T -> u2 + r2 ----------
    if (act) { GEMM_PHASE(g_W2T); }
    __syncthreads();
    if (act) {
        // delta-d2 = s2*r2 + (1-s2)*u2*th2   (th2 from bf16 side-buffer)
        #pragma unroll
        for (int j = 0; j < 2; j++) {
            float2 up = unpack2(Cp[8][j]);     // u2 pair
            float slo = s2r[2 * j], shi = s2r[2 * j + 1];
            float klo = (1.0f - slo) * up.x, khi = (1.0f - shi) * up.y;
            uint4 tlv = th2b[col0 + 2 * j][s];
            uint4 thv = th2b[col0 + 2 * j + 1][s];
            float tlo[8], thi[8];
            { float2 p; p = bfunpack(tlv.x); tlo[0] = p.x; tlo[1] = p.y;
              p = bfunpack(tlv.y); tlo[2] = p.x; tlo[3] = p.y;
              p = bfunpack(tlv.z); tlo[4] = p.x; tlo[5] = p.y;
              p = bfunpack(tlv.w); tlo[6] = p.x; tlo[7] = p.y;
              p = bfunpack(thv.x); thi[0] = p.x; thi[1] = p.y;
              p = bfunpack(thv.y); thi[2] = p.x; thi[3] = p.y;
              p = bfunpack(thv.z); thi[4] = p.x; thi[5] = p.y;
              p = bfunpack(thv.w); thi[6] = p.x; thi[7] = p.y; }
            float vlo[9], vhi[9];
            #pragma unroll
            for (int d = 0; d < DD; d++) {
                float2 r = unpack2(Cp[d][j]);
                vlo[d] = fmaf(slo, r.x, klo * tlo[d]);
                vhi[d] = fmaf(shi, r.y, khi * thi[d]);
            }
            vlo[8] = slo * up.x; vhi[8] = shi * up.y;   // d2
            float* plo = &db[(col0 + 2 * j) * PADK + s * SLOT];
            float* phi = &db[(col0 + 2 * j + 1) * PADK + s * SLOT];
            *reinterpret_cast<float4*>(plo)     = make_float4(vlo[0], vlo[1], vlo[2], vlo[3]);
            *reinterpret_cast<float4*>(plo + 4) = make_float4(vlo[4], vlo[5], vlo[6], vlo[7]);
            plo[8] = vlo[8]; plo[9] = vlo[8];
            *reinterpret_cast<float4*>(phi)     = make_float4(vhi[0], vhi[1], vhi[2], vhi[3]);
            *reinterpret_cast<float4*>(phi + 4) = make_float4(vhi[4], vhi[5], vhi[6], vhi[7]);
            phi[8] = vhi[8]; phi[9] = vhi[8];
        }
    }
    __syncthreads();

    // ---------- phase 4: stream W1^T -> u1 + r1 ----------
    if (act) { GEMM_PHASE(g_W1T); }
    __syncthreads();
    if (act) {
        float u1[NC], co[NC];
        #pragma unroll
        for (int j = 0; j < 2; j++) {
            float2 up = unpack2(Cp[8][j]);
            u1[2 * j] = up.x; u1[2 * j + 1] = up.y;
        }
        #pragma unroll
        for (int c = 0; c < NC; c++) {
            co[c] = s1r[c] * (1.0f - s1r[c]) * u1[c];
            db[(col0 + c) * PADK + s * SLOT + 8] = s1r[c] * u1[c];   // d1
        }
        #pragma unroll
        for (int d = 0; d < DD; d++) {
            float wv[NC];
            *reinterpret_cast<float4*>(wv) = *reinterpret_cast<const float4*>(&W0[(DD + d) * HID + col0]);
            #pragma unroll
            for (int j = 0; j < 2; j++) {
                float2 r = unpack2(Cp[d][j]);
                db[(col0 + 2 * j) * PADK + s * SLOT + d]     = fmaf(s1r[2 * j],     r.x, co[2 * j]     * wv[2 * j]);
                db[(col0 + 2 * j + 1) * PADK + s * SLOT + d] = fmaf(s1r[2 * j + 1], r.y, co[2 * j + 1] * wv[2 * j + 1]);
            }
        }
    }
    __syncthreads();

    // ---------- final dots ----------
    for (int idx = warp; idx < SB * 16; idx += NW) {
        int ss = idx >> 4, m = idx & 15;
        float a = 0.0f;
        for (int k = lane; k < HID; k += 32)
            a = fmaf(W0[m * HID + k], db[k * PADK + ss * SLOT + 8], a);
        #pragma unroll
        for (int off = 16; off > 0; off >>= 1) a += __shfl_xor_sync(0xffffffffu, a, off);
        if (lane == 0) sh_g[ss][m] = a;
    }
    for (int idx = warp; idx < SB * 128; idx += NW) {
        int ss = idx >> 7;
        int r = idx & 127;
        int d = r >> 4, m = r & 15;
        float a = 0.0f;
        for (int k = lane; k < HID; k += 32)
            a = fmaf(W0[m * HID + k], db[k * PADK + ss * SLOT + d], a);
        #pragma unroll
        for (int off = 16; off > 0; off >>= 1) a += __shfl_xor_sync(0xffffffffu, a, off);
        if (lane == 0) sh_H[ss][d][m] = a;
    }
    __syncthreads();

    // ---------- per-sample 8x8 solve + output ----------
    if (tid < SB && base + tid < n) {
        const int ss = tid;
        float Mt[DD][DD], Fv[DD], av[DD], vv[DD];
        #pragma unroll
        for (int c = 0; c < DD; c++) vv[c] = shz[ss][DD + c];
        for (int r = 0; r < DD; r++)
            for (int c = 0; c < DD; c++)
                Mt[r][c] = sh_H[ss][r][DD + c] + ((r == c) ? 2.0f * EPSV : 0.0f);
        for (int p = 0; p < DD; p++) {
            float f = sh_g[ss][p];
            for (int c = 0; c < DD; c++) f -= sh_H[ss][p][c] * vv[c];
            Fv[p] = f;
        }
        for (int col = 0; col < DD; col++) {
            int piv = col; float best = fabsf(Mt[col][col]);
            for (int r = col + 1; r < DD; r++) {
                float m = fabsf(Mt[r][col]);
                if (m > best) { best = m; piv = r; }
            }
            if (piv != col) {
                for (int c = col; c < DD; c++) { float t = Mt[col][c]; Mt[col][c] = Mt[piv][c]; Mt[piv][c] = t; }
                float t = Fv[col]; Fv[col] = Fv[piv]; Fv[piv] = t;
            }
            float inv = 1.0f / Mt[col][col];
            for (int r = col + 1; r < DD; r++) {
                float fac = Mt[r][col] * inv;
                for (int c = col; c < DD; c++) Mt[r][c] -= fac * Mt[col][c];
                Fv[r] -= fac * Fv[col];
            }
        }
        for (int r = DD - 1; r >= 0; r--) {
            float x = Fv[r];
            for (int c = r + 1; c < DD; c++) x -= Mt[r][c] * av[c];
            av[r] = x / Mt[r][r];
        }
        const int gi = (base + ss) * 16;
        #pragma unroll
        for (int j = 0; j < DD; j++) out[gi + j] = vv[j];
        #pragma unroll
        for (int j = 0; j < DD; j++) out[gi + DD + j] = av[j];
    }
}

extern "C" void kernel_launch(void* const* d_in, const int* in_sizes, int n_in,
                              void* d_out, int out_size) {
    const float* z  = (const float*)d_in[1];
    const float* W0 = (const float*)d_in[2];
    const float* b0 = (const float*)d_in[3];
    const float* W1 = (const float*)d_in[4];
    const float* b1 = (const float*)d_in[5];
    const float* W2 = (const float*)d_in[6];
    const float* b2 = (const float*)d_in[7];
    const float* W3 = (const float*)d_in[8];
    float* out = (float*)d_out;

    const int n = in_sizes[1] / 16;

    cudaFuncSetAttribute(lnn_kernel, cudaFuncAttributeMaxDynamicSharedMemorySize, DSMEM);

    transposeW<<<(HID * HID + 255) / 256, 256>>>(W1, W2);

    const int blocks = (n + SB - 1) / SB;
    lnn_kernel<<<blocks, NTH, DSMEM>>>(z, W0, b0, W1, b1, W2, b2, W3, out, n);
}